// round 2
// baseline (speedup 1.0000x reference)
#include <cuda_runtime.h>
#include <math.h>

// Problem constants
#define NIN   1024
#define NHEAD 16
#define HDIM  64
#define BATCH 2
#define SEQ   2048
#define MTOT  (BATCH * SEQ)   // 4096 rows for projection GEMMs

// ---------------------------------------------------------------------------
// Scratch (device globals; no allocation allowed in kernel_launch)
// ---------------------------------------------------------------------------
__device__ float g_q[BATCH * NHEAD * SEQ * HDIM];   // [B,H,N,D] 16 MB
__device__ float g_k[BATCH * NHEAD * SEQ * HDIM];
__device__ float g_v[BATCH * NHEAD * SEQ * HDIM];
__device__ float g_att[BATCH * SEQ * NIN];          // [B,N,C]   16 MB

// ---------------------------------------------------------------------------
// Shared 128x128x16 fp32 GEMM body: C = A[M,K] * W[N,K]^T
// 256 threads, 8x8 microtile per thread. K = NIN = 1024 (hardcoded).
// ---------------------------------------------------------------------------
__device__ __forceinline__ void gemm128_body(
    const float* __restrict__ A, const float* __restrict__ W,
    float (&As)[16][132], float (&Bs)[16][132], float (&acc)[8][8])
{
    const int tid  = threadIdx.x;
    const int lrow = tid >> 2;          // 0..63
    const int lcol = (tid & 3) << 2;    // 0,4,8,12
    const int tx   = tid & 15;
    const int ty   = tid >> 4;
    const int mBase = blockIdx.y * 128;
    const int nBase = blockIdx.x * 128;

    for (int k0 = 0; k0 < NIN; k0 += 16) {
#pragma unroll
        for (int r = 0; r < 2; r++) {
            const int row = lrow + r * 64;
            float4 va = *(const float4*)(A + (size_t)(mBase + row) * NIN + k0 + lcol);
            As[lcol + 0][row] = va.x;
            As[lcol + 1][row] = va.y;
            As[lcol + 2][row] = va.z;
            As[lcol + 3][row] = va.w;
            float4 vb = *(const float4*)(W + (size_t)(nBase + row) * NIN + k0 + lcol);
            Bs[lcol + 0][row] = vb.x;
            Bs[lcol + 1][row] = vb.y;
            Bs[lcol + 2][row] = vb.z;
            Bs[lcol + 3][row] = vb.w;
        }
        __syncthreads();
#pragma unroll
        for (int k = 0; k < 16; k++) {
            float a[8], b[8];
            *(float4*)&a[0] = *(const float4*)&As[k][ty * 8];
            *(float4*)&a[4] = *(const float4*)&As[k][ty * 8 + 4];
            *(float4*)&b[0] = *(const float4*)&Bs[k][tx * 8];
            *(float4*)&b[4] = *(const float4*)&Bs[k][tx * 8 + 4];
#pragma unroll
            for (int i = 0; i < 8; i++)
#pragma unroll
                for (int j = 0; j < 8; j++)
                    acc[i][j] = fmaf(a[i], b[j], acc[i][j]);
        }
        __syncthreads();
    }
}

// ---------------------------------------------------------------------------
// Fused QKV projection: grid (8, 32, 3); z selects q/k/v.
// Epilogue scatters into [B,H,N,D] layout.
// ---------------------------------------------------------------------------
__global__ __launch_bounds__(256) void qkv_gemm_kernel(
    const float* __restrict__ X,
    const float* __restrict__ Wq, const float* __restrict__ bq,
    const float* __restrict__ Wk, const float* __restrict__ bk,
    const float* __restrict__ Wv, const float* __restrict__ bv)
{
    const float* W;
    const float* bias;
    float* dst;
    if (blockIdx.z == 0)      { W = Wq; bias = bq; dst = g_q; }
    else if (blockIdx.z == 1) { W = Wk; bias = bk; dst = g_k; }
    else                      { W = Wv; bias = bv; dst = g_v; }

    __shared__ float As[16][132];
    __shared__ float Bs[16][132];
    float acc[8][8];
#pragma unroll
    for (int i = 0; i < 8; i++)
#pragma unroll
        for (int j = 0; j < 8; j++) acc[i][j] = 0.f;

    gemm128_body(X, W, As, Bs, acc);

    const int tx = threadIdx.x & 15;
    const int ty = threadIdx.x >> 4;
    const int mBase = blockIdx.y * 128;
    const int nBase = blockIdx.x * 128;

    float bv8[8];
#pragma unroll
    for (int j = 0; j < 8; j++) bv8[j] = bias[nBase + tx * 8 + j];

#pragma unroll
    for (int i = 0; i < 8; i++) {
        const int gm   = mBase + ty * 8 + i;
        const int b    = gm >> 11;          // / 2048
        const int nrow = gm & 2047;
#pragma unroll
        for (int j = 0; j < 8; j++) {
            const int gn = nBase + tx * 8 + j;
            const int h  = gn >> 6;          // / 64
            const int d  = gn & 63;
            dst[((size_t)(b * NHEAD + h) * SEQ + nrow) * HDIM + d] = acc[i][j] + bv8[j];
        }
    }
}

// ---------------------------------------------------------------------------
// Output projection: out = g_att[M,C] @ Wo^T + bo  -> d_out [B,N,C]
// grid (8, 32)
// ---------------------------------------------------------------------------
__global__ __launch_bounds__(256) void out_gemm_kernel(
    const float* __restrict__ Wo, const float* __restrict__ bo,
    float* __restrict__ out)
{
    __shared__ float As[16][132];
    __shared__ float Bs[16][132];
    float acc[8][8];
#pragma unroll
    for (int i = 0; i < 8; i++)
#pragma unroll
        for (int j = 0; j < 8; j++) acc[i][j] = 0.f;

    gemm128_body(g_att, Wo, As, Bs, acc);

    const int tx = threadIdx.x & 15;
    const int ty = threadIdx.x >> 4;
    const int mBase = blockIdx.y * 128;
    const int nBase = blockIdx.x * 128;

    float bv8[8];
#pragma unroll
    for (int j = 0; j < 8; j++) bv8[j] = bo[nBase + tx * 8 + j];

#pragma unroll
    for (int i = 0; i < 8; i++) {
        const int gm = mBase + ty * 8 + i;
        float* row = out + (size_t)gm * NIN + nBase + tx * 8;
        float4 r0 = make_float4(acc[i][0] + bv8[0], acc[i][1] + bv8[1],
                                acc[i][2] + bv8[2], acc[i][3] + bv8[3]);
        float4 r1 = make_float4(acc[i][4] + bv8[4], acc[i][5] + bv8[5],
                                acc[i][6] + bv8[6], acc[i][7] + bv8[7]);
        *(float4*)(row)     = r0;
        *(float4*)(row + 4) = r1;
    }
}

// ---------------------------------------------------------------------------
// Flash attention: one block per (b*h, 64-query tile).
// 256 threads (16x16). Online softmax, P staged through smem for PV.
// Dynamic smem: Qs/Ks/Vs/Ps each [64][68] fp32 = 69632 B.
// ---------------------------------------------------------------------------
#define APAD 68
#define ATT_SMEM (4 * 64 * APAD * 4)

__global__ __launch_bounds__(256) void attn_kernel()
{
    extern __shared__ float sm[];
    float* Qs = sm;                   // [d][q] transposed
    float* Ks = Qs + 64 * APAD;       // [d][k] transposed
    float* Vs = Ks + 64 * APAD;       // [k][d] natural
    float* Ps = Vs + 64 * APAD;       // [k][q] transposed

    const int tid = threadIdx.x;
    const int tx  = tid & 15;
    const int ty  = tid >> 4;
    const int bh  = blockIdx.y;               // 0..31  (b*16 + h)
    const int q0  = blockIdx.x * 64;

    const float* Qg = g_q + (size_t)bh * SEQ * HDIM;
    const float* Kg = g_k + (size_t)bh * SEQ * HDIM;
    const float* Vg = g_v + (size_t)bh * SEQ * HDIM;

    // Load Q tile transposed: Qs[d][row]
    for (int i = tid; i < 64 * 16; i += 256) {
        const int row = i >> 4;
        const int d4  = (i & 15) << 2;
        float4 v = *(const float4*)(Qg + (size_t)(q0 + row) * HDIM + d4);
        Qs[(d4 + 0) * APAD + row] = v.x;
        Qs[(d4 + 1) * APAD + row] = v.y;
        Qs[(d4 + 2) * APAD + row] = v.z;
        Qs[(d4 + 3) * APAD + row] = v.w;
    }

    float o[4][4];
    float mrow[4], lrow[4];
#pragma unroll
    for (int i = 0; i < 4; i++) {
        mrow[i] = -1e30f;
        lrow[i] = 0.f;
#pragma unroll
        for (int j = 0; j < 4; j++) o[i][j] = 0.f;
    }

    for (int k0 = 0; k0 < SEQ; k0 += 64) {
        // Load K (transposed) and V (natural)
        for (int i = tid; i < 64 * 16; i += 256) {
            const int row = i >> 4;
            const int d4  = (i & 15) << 2;
            float4 kv = *(const float4*)(Kg + (size_t)(k0 + row) * HDIM + d4);
            Ks[(d4 + 0) * APAD + row] = kv.x;
            Ks[(d4 + 1) * APAD + row] = kv.y;
            Ks[(d4 + 2) * APAD + row] = kv.z;
            Ks[(d4 + 3) * APAD + row] = kv.w;
            float4 vv = *(const float4*)(Vg + (size_t)(k0 + row) * HDIM + d4);
            *(float4*)&Vs[row * APAD + d4] = vv;
        }
        __syncthreads();

        // S = Q K^T * 1/sqrt(D)
        float s[4][4];
#pragma unroll
        for (int i = 0; i < 4; i++)
#pragma unroll
            for (int j = 0; j < 4; j++) s[i][j] = 0.f;

#pragma unroll 8
        for (int d = 0; d < 64; d++) {
            float4 qa = *(const float4*)&Qs[d * APAD + ty * 4];
            float4 kb = *(const float4*)&Ks[d * APAD + tx * 4];
            const float a[4] = {qa.x, qa.y, qa.z, qa.w};
            const float b[4] = {kb.x, kb.y, kb.z, kb.w};
#pragma unroll
            for (int i = 0; i < 4; i++)
#pragma unroll
                for (int j = 0; j < 4; j++)
                    s[i][j] = fmaf(a[i], b[j], s[i][j]);
        }

        // Online softmax (row reductions across tx via shuffle)
#pragma unroll
        for (int i = 0; i < 4; i++) {
            float mx = -1e30f;
#pragma unroll
            for (int j = 0; j < 4; j++) {
                s[i][j] *= 0.125f;             // 1/sqrt(64)
                mx = fmaxf(mx, s[i][j]);
            }
#pragma unroll
            for (int off = 1; off < 16; off <<= 1)
                mx = fmaxf(mx, __shfl_xor_sync(0xffffffffu, mx, off));

            const float mnew = fmaxf(mrow[i], mx);
            const float corr = __expf(mrow[i] - mnew);
            mrow[i] = mnew;

            float rsum = 0.f;
#pragma unroll
            for (int j = 0; j < 4; j++) {
                const float p = __expf(s[i][j] - mnew);
                s[i][j] = p;
                rsum += p;
            }
#pragma unroll
            for (int off = 1; off < 16; off <<= 1)
                rsum += __shfl_xor_sync(0xffffffffu, rsum, off);

            lrow[i] = lrow[i] * corr + rsum;
#pragma unroll
            for (int j = 0; j < 4; j++) o[i][j] *= corr;
        }

        // Stage P transposed: Ps[kcol][qrow]
#pragma unroll
        for (int j = 0; j < 4; j++)
#pragma unroll
            for (int i = 0; i < 4; i++)
                Ps[(tx * 4 + j) * APAD + ty * 4 + i] = s[i][j];
        __syncthreads();

        // O += P @ V
#pragma unroll 8
        for (int k = 0; k < 64; k++) {
            float4 pp = *(const float4*)&Ps[k * APAD + ty * 4];
            float4 vv = *(const float4*)&Vs[k * APAD + tx * 4];
            const float p[4] = {pp.x, pp.y, pp.z, pp.w};
            const float v[4] = {vv.x, vv.y, vv.z, vv.w};
#pragma unroll
            for (int i = 0; i < 4; i++)
#pragma unroll
                for (int j = 0; j < 4; j++)
                    o[i][j] = fmaf(p[i], v[j], o[i][j]);
        }
        __syncthreads();   // before next tile overwrites Ks/Vs/Ps
    }

    // Normalize and write to g_att in [B,N,C] layout
    const int bb = bh >> 4;
    const int h  = bh & 15;
#pragma unroll
    for (int i = 0; i < 4; i++) {
        const int gq = q0 + ty * 4 + i;
        const float inv = 1.f / lrow[i];
        float4 r = make_float4(o[i][0] * inv, o[i][1] * inv,
                               o[i][2] * inv, o[i][3] * inv);
        *(float4*)(g_att + ((size_t)(bb * SEQ + gq) * NIN) + h * HDIM + tx * 4) = r;
    }
}

// ---------------------------------------------------------------------------
// Launch
// ---------------------------------------------------------------------------
extern "C" void kernel_launch(void* const* d_in, const int* in_sizes, int n_in,
                              void* d_out, int out_size)
{
    (void)in_sizes; (void)n_in; (void)out_size;
    const float* x  = (const float*)d_in[0];
    const float* Wq = (const float*)d_in[1];
    const float* bq = (const float*)d_in[2];
    const float* Wk = (const float*)d_in[3];
    const float* bk = (const float*)d_in[4];
    const float* Wv = (const float*)d_in[5];
    const float* bv = (const float*)d_in[6];
    const float* Wo = (const float*)d_in[7];
    const float* bo = (const float*)d_in[8];
    float* out = (float*)d_out;

    // Host-side, non-allocating, idempotent; legal under graph capture.
    cudaFuncSetAttribute(attn_kernel,
                         cudaFuncAttributeMaxDynamicSharedMemorySize, ATT_SMEM);

    // 1) QKV projections (fused via grid.z)
    qkv_gemm_kernel<<<dim3(NIN / 128, MTOT / 128, 3), 256>>>(x, Wq, bq, Wk, bk, Wv, bv);

    // 2) Flash attention: grid (q tiles, b*h)
    attn_kernel<<<dim3(SEQ / 64, BATCH * NHEAD), 256, ATT_SMEM>>>();

    // 3) Output projection
    out_gemm_kernel<<<dim3(NIN / 128, MTOT / 128), 256>>>(Wo, bo, out);
}

// round 4
// speedup vs baseline: 2.4366x; 2.4366x over previous
#include <cuda_runtime.h>
#include <cuda_bf16.h>
#include <stdint.h>

// Problem constants
#define NIN   1024
#define NHEAD 16
#define HDIM  64
#define BATCH 2
#define SEQ   2048
#define MTOT  4096
#define BH    (BATCH * NHEAD)   // 32

// ---------------------------------------------------------------------------
// Device-global scratch (no allocation allowed)
// ---------------------------------------------------------------------------
__device__ __align__(128) float g_q[BH * SEQ * HDIM];
__device__ __align__(128) float g_k[BH * SEQ * HDIM];
__device__ __align__(128) float g_v[BH * SEQ * HDIM];
__device__ __align__(128) float g_att[MTOT * NIN];

__device__ __align__(128) __nv_bfloat16 g_xh[MTOT * NIN];
__device__ __align__(128) __nv_bfloat16 g_xl[MTOT * NIN];
__device__ __align__(128) __nv_bfloat16 g_wh[4 * NIN * NIN];
__device__ __align__(128) __nv_bfloat16 g_wl[4 * NIN * NIN];
__device__ __align__(128) __nv_bfloat16 g_kh[BH * SEQ * HDIM];
__device__ __align__(128) __nv_bfloat16 g_kl[BH * SEQ * HDIM];
__device__ __align__(128) __nv_bfloat16 g_vth[BH * HDIM * SEQ];  // transposed [bh][d][s]
__device__ __align__(128) __nv_bfloat16 g_vtl[BH * HDIM * SEQ];
__device__ __align__(128) __nv_bfloat16 g_ath[MTOT * NIN];
__device__ __align__(128) __nv_bfloat16 g_atl[MTOT * NIN];

// ---------------------------------------------------------------------------
// Helpers (sm_80-level only: cp.async + mma.sync — NO tcgen05, NO 'a' features)
// ---------------------------------------------------------------------------
__device__ __forceinline__ uint32_t smem_u32(const void* p) {
    uint32_t a;
    asm("{ .reg .u64 t; cvta.to.shared.u64 t, %1; cvt.u32.u64 %0, t; }" : "=r"(a) : "l"(p));
    return a;
}
__device__ __forceinline__ void cp16(uint32_t dst, const void* src) {
    asm volatile("cp.async.cg.shared.global [%0], [%1], 16;" :: "r"(dst), "l"(src));
}
#define CP_COMMIT() asm volatile("cp.async.commit_group;" ::: "memory")
#define CP_WAIT(n)  asm volatile("cp.async.wait_group %0;" :: "n"(n) : "memory")

__device__ __forceinline__ uint32_t lds32(uint32_t addr) {
    uint32_t v;
    asm volatile("ld.shared.b32 %0, [%1];" : "=r"(v) : "r"(addr));
    return v;
}
__device__ __forceinline__ void sts32(uint32_t addr, uint32_t v) {
    asm volatile("st.shared.b32 [%0], %1;" :: "r"(addr), "r"(v));
}

// m16n8k16 bf16 MMA, fp32 accum (sm_80 feature; legacy HMMA on Blackwell)
__device__ __forceinline__ void mma_bf16(float (&c)[4], const uint32_t (&a)[4],
                                         const uint32_t (&b)[2]) {
    asm volatile(
        "mma.sync.aligned.m16n8k16.row.col.f32.bf16.bf16.f32 "
        "{%0,%1,%2,%3}, {%4,%5,%6,%7}, {%8,%9}, {%0,%1,%2,%3};"
        : "+f"(c[0]), "+f"(c[1]), "+f"(c[2]), "+f"(c[3])
        : "r"(a[0]), "r"(a[1]), "r"(a[2]), "r"(a[3]), "r"(b[0]), "r"(b[1]));
}

__device__ __forceinline__ void split_pack(float x, float y, uint32_t& h, uint32_t& l) {
    __nv_bfloat16 hx = __float2bfloat16(x), hy = __float2bfloat16(y);
    __nv_bfloat16 lx = __float2bfloat16(x - __bfloat162float(hx));
    __nv_bfloat16 ly = __float2bfloat16(y - __bfloat162float(hy));
    __nv_bfloat162 hp, lp;
    hp.x = hx; hp.y = hy; lp.x = lx; lp.y = ly;
    h = *(uint32_t*)&hp; l = *(uint32_t*)&lp;
}

// ---------------------------------------------------------------------------
// fp32 -> bf16 hi/lo split (elementwise, vectorized by 4)
// ---------------------------------------------------------------------------
__global__ __launch_bounds__(256) void split_kernel(const float* __restrict__ src,
                                                    __nv_bfloat16* __restrict__ hi,
                                                    __nv_bfloat16* __restrict__ lo, int n4) {
    int i = blockIdx.x * 256 + threadIdx.x;
    if (i >= n4) return;
    float4 v = ((const float4*)src)[i];
    uint32_t h0, l0, h1, l1;
    split_pack(v.x, v.y, h0, l0);
    split_pack(v.z, v.w, h1, l1);
    uint2 uh, ul;
    uh.x = h0; uh.y = h1; ul.x = l0; ul.y = l1;
    ((uint2*)hi)[i] = uh;
    ((uint2*)lo)[i] = ul;
}

// ---------------------------------------------------------------------------
// V: [bh][s][d] fp32 -> transposed bf16 hi/lo [bh][d][s].  Tiled 32x32.
// grid (SEQ/32, HDIM/32, BH), block (32, 8)
// ---------------------------------------------------------------------------
__global__ __launch_bounds__(256) void vsplitT_kernel() {
    __shared__ float t[32][33];
    const int bh = blockIdx.z, s0 = blockIdx.x * 32, d0 = blockIdx.y * 32;
    const int x = threadIdx.x, y = threadIdx.y;
    const float* src = g_v + (size_t)bh * SEQ * HDIM;
#pragma unroll
    for (int yy = y; yy < 32; yy += 8)
        t[yy][x] = src[(size_t)(s0 + yy) * HDIM + d0 + x];
    __syncthreads();
#pragma unroll
    for (int yy = y; yy < 32; yy += 8) {
        float v = t[x][yy];                      // = in[s0+x][d0+yy]
        __nv_bfloat16 h = __float2bfloat16(v);
        __nv_bfloat16 l = __float2bfloat16(v - __bfloat162float(h));
        size_t o = ((size_t)bh * HDIM + d0 + yy) * SEQ + s0 + x;
        g_vth[o] = h;
        g_vtl[o] = l;
    }
}

// ---------------------------------------------------------------------------
// Projection GEMM: C[m][n] = sum_k A[m][k] * W[n][k]  (3-term bf16 hi/lo)
// CTA 128x128, 8 warps (2m x 4n), warp 64x32. K-chunk 32 (2 ksteps), 32 chunks.
// smem stage: Ah|Al|Wh|Wl each 128 rows x 80B (pad 40 bf16) = 40960B; 2 stages.
// ---------------------------------------------------------------------------
#define P_ROWB   80
#define P_OFF_AH 0
#define P_OFF_AL (128 * P_ROWB)
#define P_OFF_BH (2 * 128 * P_ROWB)
#define P_OFF_BL (3 * 128 * P_ROWB)
#define P_STAGE  (4 * 128 * P_ROWB)          // 40960
#define GEMM_SMEM (2 * P_STAGE)              // 81920

__device__ __forceinline__ void proj_load_chunk(
    const __nv_bfloat16* __restrict__ Ah, const __nv_bfloat16* __restrict__ Al,
    const __nv_bfloat16* __restrict__ Bh, const __nv_bfloat16* __restrict__ Bl,
    int mBase, int nBase, int k0, uint32_t st)
{
    const int tid = threadIdx.x;
#pragma unroll
    for (int idx = tid; idx < 512; idx += 256) {
        const int row = idx >> 2, seg = idx & 3;          // 4 x 16B per 32-bf16 row
        const size_t ga = (size_t)(mBase + row) * NIN + k0 + seg * 8;
        const size_t gb = (size_t)(nBase + row) * NIN + k0 + seg * 8;
        const uint32_t so = row * P_ROWB + seg * 16;
        cp16(st + P_OFF_AH + so, Ah + ga);
        cp16(st + P_OFF_AL + so, Al + ga);
        cp16(st + P_OFF_BH + so, Bh + gb);
        cp16(st + P_OFF_BL + so, Bl + gb);
    }
}

__device__ __forceinline__ void gemm_body(
    const __nv_bfloat16* Ah, const __nv_bfloat16* Al,
    const __nv_bfloat16* Bh, const __nv_bfloat16* Bl,
    int mBase, int nBase, char* smem, float C[4][4][4])
{
    const uint32_t sb = smem_u32(smem);
    const int tid = threadIdx.x;
    const int wid = tid >> 5, lane = tid & 31;
    const int g = lane >> 2, t4 = lane & 3;
    const int wm = wid >> 2, wn = wid & 3;

#pragma unroll
    for (int a = 0; a < 4; a++)
#pragma unroll
        for (int b = 0; b < 4; b++)
#pragma unroll
            for (int c = 0; c < 4; c++) C[a][b][c] = 0.f;

    proj_load_chunk(Ah, Al, Bh, Bl, mBase, nBase, 0, sb);
    CP_COMMIT();

    for (int i = 0; i < 32; i++) {
        if (i < 31) {
            proj_load_chunk(Ah, Al, Bh, Bl, mBase, nBase, (i + 1) * 32,
                            sb + ((i + 1) & 1) * P_STAGE);
            CP_COMMIT();
            CP_WAIT(1);
        } else {
            CP_WAIT(0);
        }
        __syncthreads();

        const uint32_t st = sb + (i & 1) * P_STAGE;
#pragma unroll
        for (int ks = 0; ks < 2; ks++) {
            const uint32_t cb = ks * 32 + t4 * 4;   // byte offset of k-col within row
            uint32_t ah[4][4], al[4][4], bh[4][2], bl[4][2];
#pragma unroll
            for (int mt = 0; mt < 4; mt++) {
                const uint32_t r0 = (wm * 64 + mt * 16 + g) * P_ROWB;
                const uint32_t r1 = r0 + 8 * P_ROWB;
                ah[mt][0] = lds32(st + P_OFF_AH + r0 + cb);
                ah[mt][1] = lds32(st + P_OFF_AH + r1 + cb);
                ah[mt][2] = lds32(st + P_OFF_AH + r0 + cb + 16);
                ah[mt][3] = lds32(st + P_OFF_AH + r1 + cb + 16);
                al[mt][0] = lds32(st + P_OFF_AL + r0 + cb);
                al[mt][1] = lds32(st + P_OFF_AL + r1 + cb);
                al[mt][2] = lds32(st + P_OFF_AL + r0 + cb + 16);
                al[mt][3] = lds32(st + P_OFF_AL + r1 + cb + 16);
            }
#pragma unroll
            for (int nt = 0; nt < 4; nt++) {
                const uint32_t rn = (wn * 32 + nt * 8 + g) * P_ROWB;
                bh[nt][0] = lds32(st + P_OFF_BH + rn + cb);
                bh[nt][1] = lds32(st + P_OFF_BH + rn + cb + 16);
                bl[nt][0] = lds32(st + P_OFF_BL + rn + cb);
                bl[nt][1] = lds32(st + P_OFF_BL + rn + cb + 16);
            }
#pragma unroll
            for (int mt = 0; mt < 4; mt++)
#pragma unroll
                for (int nt = 0; nt < 4; nt++) {
                    mma_bf16(C[mt][nt], ah[mt], bh[nt]);
                    mma_bf16(C[mt][nt], ah[mt], bl[nt]);
                    mma_bf16(C[mt][nt], al[mt], bh[nt]);
                }
        }
        __syncthreads();
    }
}

// QKV projection: scatter into [B,H,N,D].  grid (8, 32, 3)
__global__ __launch_bounds__(256) void qkv_tc_kernel(
    const float* __restrict__ bq, const float* __restrict__ bk, const float* __restrict__ bv)
{
    extern __shared__ char smem[];
    const int z = blockIdx.z;
    const __nv_bfloat16* Wh = g_wh + (size_t)z * NIN * NIN;
    const __nv_bfloat16* Wl = g_wl + (size_t)z * NIN * NIN;
    const float* bias = (z == 0) ? bq : (z == 1) ? bk : bv;
    float* dst = (z == 0) ? g_q : (z == 1) ? g_k : g_v;

    const int mBase = blockIdx.y * 128;
    const int nBase = blockIdx.x * 128;

    float C[4][4][4];
    gemm_body(g_xh, g_xl, Wh, Wl, mBase, nBase, smem, C);

    const int tid = threadIdx.x, wid = tid >> 5, lane = tid & 31;
    const int g = lane >> 2, t4 = lane & 3;
    const int wm = wid >> 2, wn = wid & 3;

#pragma unroll
    for (int mt = 0; mt < 4; mt++) {
        const int m0 = mBase + wm * 64 + mt * 16 + g;
        const int m1 = m0 + 8;
        const int b0 = m0 >> 11, nr0 = m0 & 2047;
        const int b1 = m1 >> 11, nr1 = m1 & 2047;
#pragma unroll
        for (int nt = 0; nt < 4; nt++) {
            const int n = nBase + wn * 32 + nt * 8 + t4 * 2;
            const int h = n >> 6, d = n & 63;
            const float2 bb = *(const float2*)(bias + n);
            float2 v0 = make_float2(C[mt][nt][0] + bb.x, C[mt][nt][1] + bb.y);
            float2 v1 = make_float2(C[mt][nt][2] + bb.x, C[mt][nt][3] + bb.y);
            *(float2*)(dst + ((size_t)(b0 * NHEAD + h) * SEQ + nr0) * HDIM + d) = v0;
            *(float2*)(dst + ((size_t)(b1 * NHEAD + h) * SEQ + nr1) * HDIM + d) = v1;
        }
    }
}

// O projection: plain [M][NIN] store.  grid (8, 32)
__global__ __launch_bounds__(256) void out_tc_kernel(
    const float* __restrict__ bo, float* __restrict__ out)
{
    extern __shared__ char smem[];
    const int mBase = blockIdx.y * 128;
    const int nBase = blockIdx.x * 128;

    float C[4][4][4];
    gemm_body(g_ath, g_atl, g_wh + 3 * NIN * NIN, g_wl + 3 * NIN * NIN,
              mBase, nBase, smem, C);

    const int tid = threadIdx.x, wid = tid >> 5, lane = tid & 31;
    const int g = lane >> 2, t4 = lane & 3;
    const int wm = wid >> 2, wn = wid & 3;

#pragma unroll
    for (int mt = 0; mt < 4; mt++) {
        const int m0 = mBase + wm * 64 + mt * 16 + g;
#pragma unroll
        for (int nt = 0; nt < 4; nt++) {
            const int n = nBase + wn * 32 + nt * 8 + t4 * 2;
            const float2 bb = *(const float2*)(bo + n);
            float2 v0 = make_float2(C[mt][nt][0] + bb.x, C[mt][nt][1] + bb.y);
            float2 v1 = make_float2(C[mt][nt][2] + bb.x, C[mt][nt][3] + bb.y);
            *(float2*)(out + (size_t)m0 * NIN + n) = v0;
            *(float2*)(out + (size_t)(m0 + 8) * NIN + n) = v1;
        }
    }
}

// ---------------------------------------------------------------------------
// Tensor-core flash attention.
// CTA: 128 q rows (8 warps x 16 rows), seq chunks of 64, 3-term bf16 hi/lo.
// K smem natural [s][d]; V smem pre-transposed [d][s]; P per-warp [16][72].
// Rows padded to 72 bf16 (144B).
// ---------------------------------------------------------------------------
#define A_ROWB    144
#define A_KV      (64 * A_ROWB)              // 9216 per tensor per stage
#define A_OFF_KH  0
#define A_OFF_KL  (2 * A_KV)
#define A_OFF_VH  (4 * A_KV)
#define A_OFF_VL  (6 * A_KV)
#define A_OFF_PH  (8 * A_KV)                 // 73728
#define A_OFF_PL  (A_OFF_PH + 8 * 16 * A_ROWB)
#define ATT_SMEM  (A_OFF_PL + 8 * 16 * A_ROWB)   // 110592

__global__ __launch_bounds__(256) void attn_tc_kernel()
{
    extern __shared__ char smem[];
    const uint32_t sb = smem_u32(smem);
    const int tid = threadIdx.x;
    const int w = tid >> 5, lane = tid & 31;
    const int g = lane >> 2, t4 = lane & 3;
    const int bh = blockIdx.y;
    const int q0 = blockIdx.x * 128;

    const float* Qg = g_q + (size_t)bh * SEQ * HDIM;
    const __nv_bfloat16* Khg = g_kh + (size_t)bh * SEQ * HDIM;
    const __nv_bfloat16* Klg = g_kl + (size_t)bh * SEQ * HDIM;
    const __nv_bfloat16* Vhg = g_vth + (size_t)bh * HDIM * SEQ;
    const __nv_bfloat16* Vlg = g_vtl + (size_t)bh * HDIM * SEQ;

    // --- Q fragments (held in registers for entire kernel) ---
    const int r0 = q0 + w * 16 + g, r1 = r0 + 8;
    uint32_t qh[4][4], ql[4][4];
#pragma unroll
    for (int ks = 0; ks < 4; ks++) {
        const int c0 = ks * 16 + t4 * 2;
        float2 a00 = *(const float2*)(Qg + (size_t)r0 * HDIM + c0);
        float2 a10 = *(const float2*)(Qg + (size_t)r1 * HDIM + c0);
        float2 a01 = *(const float2*)(Qg + (size_t)r0 * HDIM + c0 + 8);
        float2 a11 = *(const float2*)(Qg + (size_t)r1 * HDIM + c0 + 8);
        split_pack(a00.x, a00.y, qh[ks][0], ql[ks][0]);
        split_pack(a10.x, a10.y, qh[ks][1], ql[ks][1]);
        split_pack(a01.x, a01.y, qh[ks][2], ql[ks][2]);
        split_pack(a11.x, a11.y, qh[ks][3], ql[ks][3]);
    }

    float O[8][4];
#pragma unroll
    for (int nt = 0; nt < 8; nt++)
#pragma unroll
        for (int c = 0; c < 4; c++) O[nt][c] = 0.f;
    float mrow0 = -1e30f, mrow1 = -1e30f, lrow0 = 0.f, lrow1 = 0.f;

    const uint32_t pwh = sb + A_OFF_PH + w * 16 * A_ROWB;
    const uint32_t pwl = sb + A_OFF_PL + w * 16 * A_ROWB;

    // chunk loader: K rows [s][d], V rows [d][s] (both 64x64 bf16, 8 x 16B per row)
    auto load_kv = [&](int k0, int st) {
#pragma unroll
        for (int idx = tid; idx < 512; idx += 256) {
            const int row = idx >> 3, seg = idx & 7;
            const uint32_t so = st * A_KV + row * A_ROWB + seg * 16;
            cp16(sb + A_OFF_KH + so, Khg + (size_t)(k0 + row) * HDIM + seg * 8);
            cp16(sb + A_OFF_KL + so, Klg + (size_t)(k0 + row) * HDIM + seg * 8);
            cp16(sb + A_OFF_VH + so, Vhg + (size_t)row * SEQ + k0 + seg * 8);
            cp16(sb + A_OFF_VL + so, Vlg + (size_t)row * SEQ + k0 + seg * 8);
        }
    };

    load_kv(0, 0);
    CP_COMMIT();

    for (int i = 0; i < SEQ / 64; i++) {
        if (i < SEQ / 64 - 1) {
            load_kv((i + 1) * 64, (i + 1) & 1);
            CP_COMMIT();
            CP_WAIT(1);
        } else {
            CP_WAIT(0);
        }
        __syncthreads();

        const uint32_t stK = sb + (i & 1) * A_KV;

        // ---- S = Q K^T (3-term) ----
        float S[8][4];
#pragma unroll
        for (int nt = 0; nt < 8; nt++)
#pragma unroll
            for (int c = 0; c < 4; c++) S[nt][c] = 0.f;

#pragma unroll
        for (int ks = 0; ks < 4; ks++) {
            const uint32_t cb = ks * 32 + t4 * 4;
#pragma unroll
            for (int nt = 0; nt < 8; nt++) {
                const uint32_t rn = (nt * 8 + g) * A_ROWB + cb;
                uint32_t kb[2], klb[2];
                kb[0]  = lds32(stK + A_OFF_KH + rn);
                kb[1]  = lds32(stK + A_OFF_KH + rn + 16);
                klb[0] = lds32(stK + A_OFF_KL + rn);
                klb[1] = lds32(stK + A_OFF_KL + rn + 16);
                mma_bf16(S[nt], qh[ks], kb);
                mma_bf16(S[nt], qh[ks], klb);
                mma_bf16(S[nt], ql[ks], kb);
            }
        }

        // ---- online softmax (rows g and g+8; cols spread over 4 lanes) ----
        float mx0 = -1e30f, mx1 = -1e30f;
#pragma unroll
        for (int nt = 0; nt < 8; nt++) {
#pragma unroll
            for (int c = 0; c < 4; c++) S[nt][c] *= 0.125f;
            mx0 = fmaxf(mx0, fmaxf(S[nt][0], S[nt][1]));
            mx1 = fmaxf(mx1, fmaxf(S[nt][2], S[nt][3]));
        }
        mx0 = fmaxf(mx0, __shfl_xor_sync(0xffffffffu, mx0, 1));
        mx0 = fmaxf(mx0, __shfl_xor_sync(0xffffffffu, mx0, 2));
        mx1 = fmaxf(mx1, __shfl_xor_sync(0xffffffffu, mx1, 1));
        mx1 = fmaxf(mx1, __shfl_xor_sync(0xffffffffu, mx1, 2));

        const float mn0 = fmaxf(mrow0, mx0), mn1 = fmaxf(mrow1, mx1);
        const float cr0 = __expf(mrow0 - mn0), cr1 = __expf(mrow1 - mn1);
        mrow0 = mn0; mrow1 = mn1;

        float rs0 = 0.f, rs1 = 0.f;
#pragma unroll
        for (int nt = 0; nt < 8; nt++) {
            const float p00 = __expf(S[nt][0] - mn0);
            const float p01 = __expf(S[nt][1] - mn0);
            const float p10 = __expf(S[nt][2] - mn1);
            const float p11 = __expf(S[nt][3] - mn1);
            rs0 += p00 + p01;
            rs1 += p10 + p11;
            uint32_t h0, l0, h1, l1;
            split_pack(p00, p01, h0, l0);
            split_pack(p10, p11, h1, l1);
            const uint32_t cbyte = nt * 16 + t4 * 4;
            sts32(pwh + g * A_ROWB + cbyte, h0);
            sts32(pwl + g * A_ROWB + cbyte, l0);
            sts32(pwh + (g + 8) * A_ROWB + cbyte, h1);
            sts32(pwl + (g + 8) * A_ROWB + cbyte, l1);
        }
        rs0 += __shfl_xor_sync(0xffffffffu, rs0, 1);
        rs0 += __shfl_xor_sync(0xffffffffu, rs0, 2);
        rs1 += __shfl_xor_sync(0xffffffffu, rs1, 1);
        rs1 += __shfl_xor_sync(0xffffffffu, rs1, 2);
        lrow0 = lrow0 * cr0 + rs0;
        lrow1 = lrow1 * cr1 + rs1;
#pragma unroll
        for (int nt = 0; nt < 8; nt++) {
            O[nt][0] *= cr0; O[nt][1] *= cr0;
            O[nt][2] *= cr1; O[nt][3] *= cr1;
        }
        __syncwarp();

        // ---- O += P V (3-term) ----
#pragma unroll
        for (int ks = 0; ks < 4; ks++) {
            const uint32_t cb = ks * 32 + t4 * 4;
            uint32_t pah[4], pal[4];
            pah[0] = lds32(pwh + g * A_ROWB + cb);
            pah[1] = lds32(pwh + (g + 8) * A_ROWB + cb);
            pah[2] = lds32(pwh + g * A_ROWB + cb + 16);
            pah[3] = lds32(pwh + (g + 8) * A_ROWB + cb + 16);
            pal[0] = lds32(pwl + g * A_ROWB + cb);
            pal[1] = lds32(pwl + (g + 8) * A_ROWB + cb);
            pal[2] = lds32(pwl + g * A_ROWB + cb + 16);
            pal[3] = lds32(pwl + (g + 8) * A_ROWB + cb + 16);
#pragma unroll
            for (int nt = 0; nt < 8; nt++) {
                const uint32_t rd = (nt * 8 + g) * A_ROWB + cb;
                uint32_t vb[2], vlb[2];
                vb[0]  = lds32(stK + A_OFF_VH + rd);
                vb[1]  = lds32(stK + A_OFF_VH + rd + 16);
                vlb[0] = lds32(stK + A_OFF_VL + rd);
                vlb[1] = lds32(stK + A_OFF_VL + rd + 16);
                mma_bf16(O[nt], pah, vb);
                mma_bf16(O[nt], pah, vlb);
                mma_bf16(O[nt], pal, vb);
            }
        }
        __syncthreads();
    }

    // ---- normalize + write to g_att [B,N,C] ----
    const float inv0 = 1.f / lrow0, inv1 = 1.f / lrow1;
    const int b = bh >> 4, h = bh & 15;
    float* out0 = g_att + ((size_t)(b * SEQ + r0) * NIN) + h * HDIM;
    float* out1 = g_att + ((size_t)(b * SEQ + r1) * NIN) + h * HDIM;
#pragma unroll
    for (int nt = 0; nt < 8; nt++) {
        const int col = nt * 8 + t4 * 2;
        *(float2*)(out0 + col) = make_float2(O[nt][0] * inv0, O[nt][1] * inv0);
        *(float2*)(out1 + col) = make_float2(O[nt][2] * inv1, O[nt][3] * inv1);
    }
}

// ---------------------------------------------------------------------------
// Launch
// ---------------------------------------------------------------------------
extern "C" void kernel_launch(void* const* d_in, const int* in_sizes, int n_in,
                              void* d_out, int out_size)
{
    (void)in_sizes; (void)n_in; (void)out_size;
    const float* x  = (const float*)d_in[0];
    const float* Wq = (const float*)d_in[1];
    const float* bq = (const float*)d_in[2];
    const float* Wk = (const float*)d_in[3];
    const float* bk = (const float*)d_in[4];
    const float* Wv = (const float*)d_in[5];
    const float* bv = (const float*)d_in[6];
    const float* Wo = (const float*)d_in[7];
    const float* bo = (const float*)d_in[8];
    float* out = (float*)d_out;

    void *p;
    cudaGetSymbolAddress(&p, g_xh);  __nv_bfloat16* xh  = (__nv_bfloat16*)p;
    cudaGetSymbolAddress(&p, g_xl);  __nv_bfloat16* xl  = (__nv_bfloat16*)p;
    cudaGetSymbolAddress(&p, g_wh);  __nv_bfloat16* wh  = (__nv_bfloat16*)p;
    cudaGetSymbolAddress(&p, g_wl);  __nv_bfloat16* wl  = (__nv_bfloat16*)p;
    cudaGetSymbolAddress(&p, g_kh);  __nv_bfloat16* kh  = (__nv_bfloat16*)p;
    cudaGetSymbolAddress(&p, g_kl);  __nv_bfloat16* kl  = (__nv_bfloat16*)p;
    cudaGetSymbolAddress(&p, g_ath); __nv_bfloat16* ath = (__nv_bfloat16*)p;
    cudaGetSymbolAddress(&p, g_atl); __nv_bfloat16* atl = (__nv_bfloat16*)p;
    cudaGetSymbolAddress(&p, g_k);   float* gk = (float*)p;
    cudaGetSymbolAddress(&p, g_att); float* ga = (float*)p;

    cudaFuncSetAttribute(qkv_tc_kernel, cudaFuncAttributeMaxDynamicSharedMemorySize, GEMM_SMEM);
    cudaFuncSetAttribute(out_tc_kernel, cudaFuncAttributeMaxDynamicSharedMemorySize, GEMM_SMEM);
    cudaFuncSetAttribute(attn_tc_kernel, cudaFuncAttributeMaxDynamicSharedMemorySize, ATT_SMEM);

    const int W4 = NIN * NIN / 4;       // 262144
    const int X4 = MTOT * NIN / 4;      // 1048576

    // 1) splits of x and all weights
    split_kernel<<<(X4 + 255) / 256, 256>>>(x,  xh, xl, X4);
    split_kernel<<<(W4 + 255) / 256, 256>>>(Wq, wh + 0 * NIN * NIN, wl + 0 * NIN * NIN, W4);
    split_kernel<<<(W4 + 255) / 256, 256>>>(Wk, wh + 1 * NIN * NIN, wl + 1 * NIN * NIN, W4);
    split_kernel<<<(W4 + 255) / 256, 256>>>(Wv, wh + 2 * NIN * NIN, wl + 2 * NIN * NIN, W4);
    split_kernel<<<(W4 + 255) / 256, 256>>>(Wo, wh + 3 * NIN * NIN, wl + 3 * NIN * NIN, W4);

    // 2) QKV projections (tensor cores)
    qkv_tc_kernel<<<dim3(NIN / 128, MTOT / 128, 3), 256, GEMM_SMEM>>>(bq, bk, bv);

    // 3) K split, V transpose+split
    split_kernel<<<(X4 + 255) / 256, 256>>>(gk, kh, kl, X4);
    vsplitT_kernel<<<dim3(SEQ / 32, HDIM / 32, BH), dim3(32, 8)>>>();

    // 4) attention (tensor cores)
    attn_tc_kernel<<<dim3(SEQ / 128, BH), 256, ATT_SMEM>>>();

    // 5) split attention output, O projection
    split_kernel<<<(X4 + 255) / 256, 256>>>(ga, ath, atl, X4);
    out_tc_kernel<<<dim3(NIN / 128, MTOT / 128), 256, GEMM_SMEM>>>(bo, out);
}